// round 4
// baseline (speedup 1.0000x reference)
#include <cuda_runtime.h>
#include <cuda_fp16.h>
#include <cstdint>

#define HID 96
#define CIN 192
#define MAXN 120000
#define EPSBN 1e-5f

// fp32 linear GEMM params
#define TM 128
#define KC 16
#define NCH (CIN / KC)

// ===== conv mma params =====
#define CTM 128                 // voxel rows per CTA
#define NSTG 162                // 27 offsets * 6 chunks of K=32
#define ASTRIDE 80              // bytes per smem row (32 fp16 = 64B + 16 pad)
#define AHPL (128 * ASTRIDE)    // 10240 B  (one A plane: hi or lo)
#define BPL (96 * ASTRIDE)      // 7680 B
#define STG (2 * AHPL + BPL)    // 28160 B per stage
#define SMEM_CONV (3 * STG)     // 84480 B

// ---- scratch (static device globals; no allocation) ----
__device__ float g_vsum[(size_t)MAXN * CIN];
__device__ float g_cnt[MAXN];
__device__ __half g_vhl[(size_t)(MAXN + 1) * 384];   // per voxel row: 192 hi, 192 lo
__device__ float g_acc[(size_t)MAXN * HID];          // conv output
__device__ float g_bn[2 * HID];
__device__ float g_ss[2 * HID];
__device__ __half g_wh[(size_t)NSTG * 96 * 32];      // fp16 weights [stage][n][k]
__device__ int g_nbrT[27 * MAXN];                    // transposed neighbor table

#define MMA_F16(d, a, b)                                                      \
    asm volatile(                                                             \
        "mma.sync.aligned.m16n8k16.row.col.f32.f16.f16.f32 "                  \
        "{%0,%1,%2,%3},{%4,%5,%6,%7},{%8,%9},{%0,%1,%2,%3};"                  \
        : "+f"((d)[0]), "+f"((d)[1]), "+f"((d)[2]), "+f"((d)[3])              \
        : "r"((a)[0]), "r"((a)[1]), "r"((a)[2]), "r"((a)[3]),                 \
          "r"((b)[0]), "r"((b)[1]))

#define CP16(dst_u32, src_ptr)                                                \
    asm volatile("cp.async.cg.shared.global [%0], [%1], 16;"                  \
                 :: "r"(dst_u32), "l"(src_ptr))
#define CP_COMMIT() asm volatile("cp.async.commit_group;" ::: "memory")
#define CP_WAIT1()  asm volatile("cp.async.wait_group 1;" ::: "memory")

__device__ __forceinline__ uint32_t smem_u32(const void* p) {
    uint32_t a;
    asm("{ .reg .u64 t; cvta.to.shared.u64 t, %1; cvt.u32.u64 %0, t; }" : "=r"(a) : "l"(p));
    return a;
}

// ---- 0a: weight prep: transpose + fp16 ----
__global__ void prep_kernel(const float* __restrict__ W) {
    int b = blockIdx.x;                  // stage = k*6 + ch
    int k = b / 6, ch = b - k * 6;
    __half* dst = g_wh + (size_t)b * 3072;
    for (int idx = threadIdx.x; idx < 3072; idx += blockDim.x) {
        int n = idx >> 5;
        int c = idx & 31;
        dst[idx] = __float2half_rn(W[((size_t)k * CIN + (ch * 32 + c)) * HID + n]);
    }
}

// ---- 0b: transpose neighbor table ----
__global__ void nbrT_kernel(const int* __restrict__ nbr, int M) {
    int idx = blockIdx.x * blockDim.x + threadIdx.x;
    if (idx >= M * 27) return;
    int m = idx / 27, k = idx - m * 27;
    g_nbrT[k * MAXN + m] = nbr[idx];
}

// ---- 1: concat + scatter-add ----
__global__ void scatter_kernel(const float* __restrict__ hF, const float* __restrict__ qF,
                               const int* __restrict__ seg, int N) {
    long long t = (long long)blockIdx.x * blockDim.x + threadIdx.x;
    if (t >= (long long)N * CIN) return;
    int n = (int)(t / CIN);
    int c = (int)(t - (long long)n * CIN);
    float v = (c < HID) ? hF[(size_t)n * HID + c] : qF[(size_t)n * HID + (c - HID)];
    int m = seg[n];
    atomicAdd(&g_vsum[(size_t)m * CIN + c], v);
    if (c == 0) atomicAdd(&g_cnt[m], 1.0f);
}

// ---- 2: divide by count + fp16 hi/lo split -> g_vhl (row M = zeros) ----
__global__ void split_kernel(int M) {
    long long t = (long long)blockIdx.x * blockDim.x + threadIdx.x;
    if (t >= (long long)(M + 1) * CIN) return;
    int m = (int)(t / CIN);
    int c = (int)(t - (long long)m * CIN);
    __half hi = __float2half_rn(0.0f), lo = __float2half_rn(0.0f);
    if (m < M) {
        float ct = g_cnt[m];
        if (ct < 1.0f) ct = 1.0f;
        float v = g_vsum[t] / ct;
        hi = __float2half_rn(v);
        lo = __float2half_rn(v - __half2float(hi));
    }
    g_vhl[(size_t)m * 384 + c] = hi;
    g_vhl[(size_t)m * 384 + 192 + c] = lo;
}

// ---- 3: sparse conv via mma.sync fp16 2-term split, cp.async 3-stage pipeline ----
__global__ __launch_bounds__(256, 2)
void conv_mma_kernel(int M) {
    extern __shared__ char smem[];
    int tid = threadIdx.x;
    int wid = tid >> 5;
    int lane = tid & 31;
    int mbase = blockIdx.x * CTM;

    int prow = tid >> 1;          // producer row 0..127
    int ppart = tid & 1;          // 32B half within 64B row
    int warp_m = wid & 3;
    int warp_n = wid >> 2;
    int r0 = lane >> 2;
    int c4 = (lane & 3) << 2;

    uint32_t sm0 = smem_u32(smem);

    float acc[2][6][4];
#pragma unroll
    for (int mt = 0; mt < 2; ++mt)
#pragma unroll
        for (int nt = 0; nt < 6; ++nt)
#pragma unroll
            for (int q = 0; q < 4; ++q) acc[mt][nt][q] = 0.0f;

    const char* vhl = (const char*)g_vhl;
    const char* whbase = (const char*)g_wh;

#define ISSUE(st) do {                                                        \
        int k_ = (st) / 6, ch_ = (st) - k_ * 6;                               \
        uint32_t buf_ = sm0 + ((st) % 3) * STG;                               \
        int m_ = mbase + prow;                                                \
        int row_ = (m_ < M) ? g_nbrT[k_ * MAXN + m_] : M;                     \
        const char* sa_ = vhl + (size_t)row_ * 768 + ch_ * 64 + ppart * 32;   \
        uint32_t da_ = buf_ + prow * ASTRIDE + ppart * 32;                    \
        CP16(da_, sa_); CP16(da_ + 16, sa_ + 16);                             \
        CP16(da_ + AHPL, sa_ + 384); CP16(da_ + AHPL + 16, sa_ + 400);        \
        const char* ws_ = whbase + (size_t)(st) * 6144;                       \
        uint32_t bb_ = buf_ + 2 * AHPL;                                       \
        CP16(bb_ + (tid >> 2) * ASTRIDE + (tid & 3) * 16, ws_ + tid * 16);    \
        if (tid < 128) {                                                      \
            int i2_ = tid + 256;                                              \
            CP16(bb_ + (i2_ >> 2) * ASTRIDE + (i2_ & 3) * 16, ws_ + i2_ * 16);\
        }                                                                     \
    } while (0)

    ISSUE(0); CP_COMMIT();
    ISSUE(1); CP_COMMIT();

    for (int it = 0; it < NSTG; ++it) {
        CP_WAIT1();
        __syncthreads();
        if (it + 2 < NSTG) ISSUE(it + 2);
        CP_COMMIT();

        const char* ahb = smem + (it % 3) * STG;
        const char* alb = ahb + AHPL;
        const char* bhb = ahb + 2 * AHPL;
#pragma unroll
        for (int s = 0; s < 2; ++s) {
            int kb = s * 32 + c4;
            uint32_t Ah[2][4], Al[2][4], Bh[6][2];
#pragma unroll
            for (int mt = 0; mt < 2; ++mt) {
                int roff = (warp_m * 32 + mt * 16 + r0) * ASTRIDE + kb;
                Ah[mt][0] = *(const uint32_t*)(ahb + roff);
                Ah[mt][1] = *(const uint32_t*)(ahb + roff + 8 * ASTRIDE);
                Ah[mt][2] = *(const uint32_t*)(ahb + roff + 16);
                Ah[mt][3] = *(const uint32_t*)(ahb + roff + 8 * ASTRIDE + 16);
                Al[mt][0] = *(const uint32_t*)(alb + roff);
                Al[mt][1] = *(const uint32_t*)(alb + roff + 8 * ASTRIDE);
                Al[mt][2] = *(const uint32_t*)(alb + roff + 16);
                Al[mt][3] = *(const uint32_t*)(alb + roff + 8 * ASTRIDE + 16);
            }
#pragma unroll
            for (int nt = 0; nt < 6; ++nt) {
                int noff = (warp_n * 48 + nt * 8 + r0) * ASTRIDE + kb;
                Bh[nt][0] = *(const uint32_t*)(bhb + noff);
                Bh[nt][1] = *(const uint32_t*)(bhb + noff + 16);
            }
#pragma unroll
            for (int nt = 0; nt < 6; ++nt) {
#pragma unroll
                for (int mt = 0; mt < 2; ++mt) {
                    MMA_F16(acc[mt][nt], Ah[mt], Bh[nt]);
                    MMA_F16(acc[mt][nt], Al[mt], Bh[nt]);
                }
            }
        }
    }

    // ---- epilogue: store acc + fused BN partial sums ----
    int cc = (lane & 3) << 1;
#pragma unroll
    for (int mt = 0; mt < 2; ++mt) {
        int row = mbase + warp_m * 32 + mt * 16 + r0;
#pragma unroll
        for (int nt = 0; nt < 6; ++nt) {
            int col = warp_n * 48 + nt * 8 + cc;
            if (row < M)
                *(float2*)(g_acc + (size_t)row * HID + col) =
                    make_float2(acc[mt][nt][0], acc[mt][nt][1]);
            if (row + 8 < M)
                *(float2*)(g_acc + (size_t)(row + 8) * HID + col) =
                    make_float2(acc[mt][nt][2], acc[mt][nt][3]);
        }
    }

    __syncthreads();
    float* bns = (float*)smem;       // [96] sums
    float* bnq = bns + 96;           // [96] sumsq
    if (tid < 192) bns[tid] = 0.0f;
    __syncthreads();
#pragma unroll
    for (int nt = 0; nt < 6; ++nt) {
        float s0 = 0.f, q0 = 0.f, s1 = 0.f, q1 = 0.f;
#pragma unroll
        for (int mt = 0; mt < 2; ++mt) {
            int row = mbase + warp_m * 32 + mt * 16 + r0;
            if (row < M) {
                float a = acc[mt][nt][0], b = acc[mt][nt][1];
                s0 += a; q0 += a * a; s1 += b; q1 += b * b;
            }
            if (row + 8 < M) {
                float a = acc[mt][nt][2], b = acc[mt][nt][3];
                s0 += a; q0 += a * a; s1 += b; q1 += b * b;
            }
        }
        int col = warp_n * 48 + nt * 8 + cc;
        atomicAdd(&bns[col], s0);
        atomicAdd(&bnq[col], q0);
        atomicAdd(&bns[col + 1], s1);
        atomicAdd(&bnq[col + 1], q1);
    }
    __syncthreads();
    if (tid < 96) {
        atomicAdd(&g_bn[tid], bns[tid]);
        atomicAdd(&g_bn[96 + tid], bnq[tid]);
    }
}

// ---- 5: BN scale/shift ----
__global__ void bnscale_kernel(const float* __restrict__ gamma,
                               const float* __restrict__ beta, int M) {
    int j = threadIdx.x;
    if (j >= HID) return;
    float inv = 1.0f / (float)M;
    float mu = g_bn[j] * inv;
    float var = g_bn[HID + j] * inv - mu * mu;
    if (var < 0.0f) var = 0.0f;
    float sc = gamma[j] * rsqrtf(var + EPSBN);
    g_ss[j] = sc;
    g_ss[HID + j] = beta[j] - mu * sc;
}

// ---- 7: residual linear GEMM (fp32 SIMT) ----
__global__ __launch_bounds__(256, 2)
void linear_kernel(const float* __restrict__ hF, const float* __restrict__ qF,
                   const float* __restrict__ Wl, const float* __restrict__ bl,
                   float* __restrict__ out, int N) {
    __shared__ float As[2][TM * (KC + 1)];
    __shared__ float Bs[2][KC * HID];

    int tid = threadIdx.x;
    int nbase = blockIdx.x * TM;
    int tr = tid >> 4;
    int tc = tid & 15;

    float acc[8][6];
#pragma unroll
    for (int i = 0; i < 8; ++i)
#pragma unroll
        for (int p = 0; p < 6; ++p) acc[i][p] = 0.0f;

    {
#pragma unroll
        for (int i = 0; i < 8; ++i) {
            int idx = i * 256 + tid;
            int c = idx & (KC - 1), r = idx >> 4;
            int n = nbase + r;
            float v = 0.0f;
            if (n < N) v = hF[(size_t)n * HID + c];
            As[0][r * (KC + 1) + c] = v;
        }
#pragma unroll
        for (int i = 0; i < 6; ++i) {
            int idx = i * 256 + tid;
            Bs[0][idx] = Wl[idx];
        }
    }
    __syncthreads();
    int buf = 0;
#pragma unroll
    for (int ch = 0; ch < NCH; ++ch) {
        float ra[8], rb[6];
        if (ch < NCH - 1) {
            int cbase = (ch + 1) * KC;
#pragma unroll
            for (int i = 0; i < 8; ++i) {
                int idx = i * 256 + tid;
                int c = idx & (KC - 1), r = idx >> 4;
                int n = nbase + r;
                int col = cbase + c;
                float v = 0.0f;
                if (n < N)
                    v = (col < HID) ? hF[(size_t)n * HID + col]
                                    : qF[(size_t)n * HID + (col - HID)];
                ra[i] = v;
            }
#pragma unroll
            for (int i = 0; i < 6; ++i) {
                int idx = i * 256 + tid;
                rb[i] = Wl[(size_t)cbase * HID + idx];
            }
        }
        const float* Ab = &As[buf][0];
        const float* Bb = &Bs[buf][0];
#pragma unroll
        for (int c = 0; c < KC; ++c) {
            float a[8], b[6];
#pragma unroll
            for (int i = 0; i < 8; ++i) a[i] = Ab[(tr * 8 + i) * (KC + 1) + c];
#pragma unroll
            for (int p = 0; p < 6; ++p) b[p] = Bb[c * HID + tc * 6 + p];
#pragma unroll
            for (int i = 0; i < 8; ++i)
#pragma unroll
                for (int p = 0; p < 6; ++p) acc[i][p] += a[i] * b[p];
        }
        if (ch < NCH - 1) {
            int nb = buf ^ 1;
#pragma unroll
            for (int i = 0; i < 8; ++i) {
                int idx = i * 256 + tid;
                int c = idx & (KC - 1), r = idx >> 4;
                As[nb][r * (KC + 1) + c] = ra[i];
            }
#pragma unroll
            for (int i = 0; i < 6; ++i) Bs[nb][i * 256 + tid] = rb[i];
            __syncthreads();
            buf = nb;
        }
    }
#pragma unroll
    for (int i = 0; i < 8; ++i) {
        int n = nbase + tr * 8 + i;
        if (n < N) {
#pragma unroll
            for (int p = 0; p < 6; ++p)
                out[(size_t)n * HID + tc * 6 + p] = acc[i][p] + bl[tc * 6 + p];
        }
    }
}

// ---- 8: trilinear gather with fused BN+ReLU ----
__global__ void trilinear_kernel(const float* __restrict__ cw, const int* __restrict__ cidx,
                                 float* __restrict__ out, int N, int M) {
    long long t = (long long)blockIdx.x * blockDim.x + threadIdx.x;
    if (t >= (long long)N * HID) return;
    int n = (int)(t / HID);
    int j = (int)(t - (long long)n * HID);
    float sc = g_ss[j];
    float sh = g_ss[HID + j];
    float s = out[t];
#pragma unroll
    for (int k = 0; k < 8; ++k) {
        int ci = cidx[(size_t)n * 8 + k];
        if (ci < M) {
            float w = cw[(size_t)n * 8 + k];
            float v = g_acc[(size_t)ci * HID + j] * sc + sh;
            v = v > 0.0f ? v : 0.0f;
            s += w * v;
        }
    }
    out[t] = s;
}

extern "C" void kernel_launch(void* const* d_in, const int* in_sizes, int n_in,
                              void* d_out, int out_size) {
    const float* hF    = (const float*)d_in[0];
    const float* qF    = (const float*)d_in[1];
    const float* Wc    = (const float*)d_in[2];
    const float* gamma = (const float*)d_in[3];
    const float* beta  = (const float*)d_in[4];
    const float* Wl    = (const float*)d_in[5];
    const float* bl    = (const float*)d_in[6];
    const float* cw    = (const float*)d_in[7];
    const int*   seg   = (const int*)d_in[8];
    const int*   nbr   = (const int*)d_in[9];
    const int*   cidx  = (const int*)d_in[10];
    float* out = (float*)d_out;

    int N = in_sizes[8];
    int M = in_sizes[9] / 27;

    cudaFuncSetAttribute(conv_mma_kernel,
                         cudaFuncAttributeMaxDynamicSharedMemorySize, SMEM_CONV);

    void *pv, *pc, *pb;
    cudaGetSymbolAddress(&pv, g_vsum);
    cudaGetSymbolAddress(&pc, g_cnt);
    cudaGetSymbolAddress(&pb, g_bn);
    cudaMemsetAsync(pv, 0, (size_t)M * CIN * sizeof(float), 0);
    cudaMemsetAsync(pc, 0, (size_t)M * sizeof(float), 0);
    cudaMemsetAsync(pb, 0, 2 * HID * sizeof(float), 0);

    prep_kernel<<<NSTG, 256>>>(Wc);
    nbrT_kernel<<<(M * 27 + 255) / 256, 256>>>(nbr, M);

    long long nt;
    nt = (long long)N * CIN;
    scatter_kernel<<<(unsigned)((nt + 255) / 256), 256>>>(hF, qF, seg, N);

    nt = (long long)(M + 1) * CIN;
    split_kernel<<<(unsigned)((nt + 255) / 256), 256>>>(M);

    conv_mma_kernel<<<(M + CTM - 1) / CTM, 256, SMEM_CONV>>>(M);

    bnscale_kernel<<<1, HID>>>(gamma, beta, M);

    linear_kernel<<<(N + TM - 1) / TM, 256>>>(hF, qF, Wl, bl, out, N);

    nt = (long long)N * HID;
    trilinear_kernel<<<(unsigned)((nt + 255) / 256), 256>>>(cw, cidx, out, N, M);
}

// round 5
// speedup vs baseline: 5.1652x; 5.1652x over previous
#include <cuda_runtime.h>
#include <cuda_fp16.h>
#include <cstdint>

#define HID 96
#define CIN 192
#define MAXN 120000
#define EPSBN 1e-5f

// fp32 linear GEMM params
#define TM 128
#define KC 16
#define NCH (CIN / KC)

// ===== conv mma params =====
#define CTM 128                 // voxel rows per CTA
#define NSTG 162                // 27 offsets * 6 chunks of K=32
#define ASTRIDE 80              // bytes per smem row (32 fp16 = 64B + 16 pad)
#define AHPL (128 * ASTRIDE)    // 10240 B (one A plane: hi or lo)
#define BPL (96 * ASTRIDE)      // 7680 B
#define STG (2 * AHPL + BPL)    // 28160 B per stage
#define SMEM_CONV (2 * STG)     // 56320 B

// ---- scratch (static device globals; no allocation) ----
__device__ float g_vsum[(size_t)MAXN * CIN];
__device__ float g_cnt[MAXN];
__device__ __half g_vhl[(size_t)(MAXN + 1) * 384];   // per voxel: 192 hi | 192 lo
__device__ float g_acc[(size_t)MAXN * HID];          // conv output
__device__ float g_bn[2 * HID];
__device__ float g_ss[2 * HID];
__device__ __half g_wh[(size_t)NSTG * 96 * 32];      // fp16 weights [stage][n][k]
__device__ int g_nbrT[27 * MAXN];                    // transposed neighbor table

#define MMA_F16(d, a, b)                                                      \
    asm volatile(                                                             \
        "mma.sync.aligned.m16n8k16.row.col.f32.f16.f16.f32 "                  \
        "{%0,%1,%2,%3},{%4,%5,%6,%7},{%8,%9},{%0,%1,%2,%3};"                  \
        : "+f"((d)[0]), "+f"((d)[1]), "+f"((d)[2]), "+f"((d)[3])              \
        : "r"((a)[0]), "r"((a)[1]), "r"((a)[2]), "r"((a)[3]),                 \
          "r"((b)[0]), "r"((b)[1]))

// ---- 0a: weight prep: transpose + fp16 ----
__global__ void prep_kernel(const float* __restrict__ W) {
    int b = blockIdx.x;                  // stage = k*6 + ch
    int k = b / 6, ch = b - k * 6;
    __half* dst = g_wh + (size_t)b * 3072;
    for (int idx = threadIdx.x; idx < 3072; idx += blockDim.x) {
        int n = idx >> 5;
        int c = idx & 31;
        dst[idx] = __float2half_rn(W[((size_t)k * CIN + (ch * 32 + c)) * HID + n]);
    }
}

// ---- 0b: transpose neighbor table ----
__global__ void nbrT_kernel(const int* __restrict__ nbr, int M) {
    int idx = blockIdx.x * blockDim.x + threadIdx.x;
    if (idx >= M * 27) return;
    int m = idx / 27, k = idx - m * 27;
    g_nbrT[k * MAXN + m] = nbr[idx];
}

// ---- 1: concat + scatter-add ----
__global__ void scatter_kernel(const float* __restrict__ hF, const float* __restrict__ qF,
                               const int* __restrict__ seg, int N) {
    long long t = (long long)blockIdx.x * blockDim.x + threadIdx.x;
    if (t >= (long long)N * CIN) return;
    int n = (int)(t / CIN);
    int c = (int)(t - (long long)n * CIN);
    float v = (c < HID) ? hF[(size_t)n * HID + c] : qF[(size_t)n * HID + (c - HID)];
    int m = seg[n];
    atomicAdd(&g_vsum[(size_t)m * CIN + c], v);
    if (c == 0) atomicAdd(&g_cnt[m], 1.0f);
}

// ---- 2: divide by count + fp16 hi/lo split -> g_vhl (row M = zeros) ----
__global__ void split_kernel(int M) {
    long long t = (long long)blockIdx.x * blockDim.x + threadIdx.x;
    if (t >= (long long)(M + 1) * CIN) return;
    int m = (int)(t / CIN);
    int c = (int)(t - (long long)m * CIN);
    __half hi = __float2half_rn(0.0f), lo = __float2half_rn(0.0f);
    if (m < M) {
        float ct = g_cnt[m];
        if (ct < 1.0f) ct = 1.0f;
        float v = g_vsum[t] / ct;
        hi = __float2half_rn(v);
        lo = __float2half_rn(v - __half2float(hi));
    }
    g_vhl[(size_t)m * 384 + c] = hi;
    g_vhl[(size_t)m * 384 + 192 + c] = lo;
}

// ---- 3: sparse conv, fp16 2-term split, R3-style double-buffered pipeline ----
__global__ __launch_bounds__(256)
void conv_mma_kernel(int M) {
    extern __shared__ char smem[];
    int tid = threadIdx.x;
    int wid = tid >> 5;
    int lane = tid & 31;
    int mbase = blockIdx.x * CTM;

    int prow = tid >> 1;          // producer row 0..127
    int ppart = tid & 1;          // 32B half within 64B row
    int warp_m = wid & 3;
    int warp_n = wid >> 2;
    int r0 = lane >> 2;
    int c4 = (lane & 3) << 2;

    float acc[2][6][4];
#pragma unroll
    for (int mt = 0; mt < 2; ++mt)
#pragma unroll
        for (int nt = 0; nt < 6; ++nt)
#pragma unroll
            for (int q = 0; q < 4; ++q) acc[mt][nt][q] = 0.0f;

    const char* vhl = (const char*)g_vhl;
    const char* whbase = (const char*)g_wh;

    // ---- produce stage 0 into buf 0 (direct LDG -> STS) ----
    {
        int m = mbase + prow;
        int row = (m < M) ? g_nbrT[0 * MAXN + m] : M;
        const char* sa = vhl + (size_t)row * 768 + ppart * 32;
        char* da = smem + prow * ASTRIDE + ppart * 32;
        *(uint4*)(da) = *(const uint4*)(sa);
        *(uint4*)(da + 16) = *(const uint4*)(sa + 16);
        *(uint4*)(da + AHPL) = *(const uint4*)(sa + 384);
        *(uint4*)(da + AHPL + 16) = *(const uint4*)(sa + 400);
        char* bb = smem + 2 * AHPL;
        const uint4* ws = (const uint4*)whbase;
        {
            uint4 v = ws[tid];
            *(uint4*)(bb + (tid >> 2) * ASTRIDE + (tid & 3) * 16) = v;
        }
        if (tid < 128) {
            int i2 = tid + 256;
            uint4 v = ws[i2];
            *(uint4*)(bb + (i2 >> 2) * ASTRIDE + (i2 & 3) * 16) = v;
        }
    }
    __syncthreads();

    for (int it = 0; it < NSTG; ++it) {
        int buf = it & 1;
        bool pf = (it + 1 < NSTG);
        uint4 va[4], vb0, vb1;

        // ---- register prefetch of next stage ----
        if (pf) {
            int st = it + 1;
            int k = st / 6, ch = st - k * 6;
            int m = mbase + prow;
            int row = (m < M) ? g_nbrT[k * MAXN + m] : M;
            const char* sa = vhl + (size_t)row * 768 + ch * 64 + ppart * 32;
            va[0] = *(const uint4*)(sa);
            va[1] = *(const uint4*)(sa + 16);
            va[2] = *(const uint4*)(sa + 384);
            va[3] = *(const uint4*)(sa + 400);
            const uint4* ws = (const uint4*)(whbase + (size_t)st * 6144);
            vb0 = ws[tid];
            if (tid < 128) vb1 = ws[tid + 256];
        }

        // ---- consume buf ----
        {
            const char* ahb = smem + buf * STG;
            const char* alb = ahb + AHPL;
            const char* bhb = ahb + 2 * AHPL;
#pragma unroll
            for (int s = 0; s < 2; ++s) {
                int kb = s * 32 + c4;
                uint32_t Ah[2][4], Al[2][4], Bh[6][2];
#pragma unroll
                for (int mt = 0; mt < 2; ++mt) {
                    int roff = (warp_m * 32 + mt * 16 + r0) * ASTRIDE + kb;
                    Ah[mt][0] = *(const uint32_t*)(ahb + roff);
                    Ah[mt][1] = *(const uint32_t*)(ahb + roff + 8 * ASTRIDE);
                    Ah[mt][2] = *(const uint32_t*)(ahb + roff + 16);
                    Ah[mt][3] = *(const uint32_t*)(ahb + roff + 8 * ASTRIDE + 16);
                    Al[mt][0] = *(const uint32_t*)(alb + roff);
                    Al[mt][1] = *(const uint32_t*)(alb + roff + 8 * ASTRIDE);
                    Al[mt][2] = *(const uint32_t*)(alb + roff + 16);
                    Al[mt][3] = *(const uint32_t*)(alb + roff + 8 * ASTRIDE + 16);
                }
#pragma unroll
                for (int nt = 0; nt < 6; ++nt) {
                    int noff = (warp_n * 48 + nt * 8 + r0) * ASTRIDE + kb;
                    Bh[nt][0] = *(const uint32_t*)(bhb + noff);
                    Bh[nt][1] = *(const uint32_t*)(bhb + noff + 16);
                }
#pragma unroll
                for (int nt = 0; nt < 6; ++nt) {
#pragma unroll
                    for (int mt = 0; mt < 2; ++mt) {
                        MMA_F16(acc[mt][nt], Ah[mt], Bh[nt]);
                        MMA_F16(acc[mt][nt], Al[mt], Bh[nt]);
                    }
                }
            }
        }

        // ---- store prefetched stage into buf^1 ----
        if (pf) {
            char* stg = smem + (buf ^ 1) * STG;
            char* da = stg + prow * ASTRIDE + ppart * 32;
            *(uint4*)(da) = va[0];
            *(uint4*)(da + 16) = va[1];
            *(uint4*)(da + AHPL) = va[2];
            *(uint4*)(da + AHPL + 16) = va[3];
            char* bb = stg + 2 * AHPL;
            *(uint4*)(bb + (tid >> 2) * ASTRIDE + (tid & 3) * 16) = vb0;
            if (tid < 128) {
                int i2 = tid + 256;
                *(uint4*)(bb + (i2 >> 2) * ASTRIDE + (i2 & 3) * 16) = vb1;
            }
        }
        __syncthreads();
    }

    // ---- epilogue: store acc + fused BN partial sums ----
    int cc = (lane & 3) << 1;
#pragma unroll
    for (int mt = 0; mt < 2; ++mt) {
        int row = mbase + warp_m * 32 + mt * 16 + r0;
#pragma unroll
        for (int nt = 0; nt < 6; ++nt) {
            int col = warp_n * 48 + nt * 8 + cc;
            if (row < M)
                *(float2*)(g_acc + (size_t)row * HID + col) =
                    make_float2(acc[mt][nt][0], acc[mt][nt][1]);
            if (row + 8 < M)
                *(float2*)(g_acc + (size_t)(row + 8) * HID + col) =
                    make_float2(acc[mt][nt][2], acc[mt][nt][3]);
        }
    }

    __syncthreads();
    float* bns = (float*)smem;       // [96] sums
    float* bnq = bns + 96;           // [96] sumsq
    if (tid < 192) bns[tid] = 0.0f;
    __syncthreads();
#pragma unroll
    for (int nt = 0; nt < 6; ++nt) {
        float s0 = 0.f, q0 = 0.f, s1 = 0.f, q1 = 0.f;
#pragma unroll
        for (int mt = 0; mt < 2; ++mt) {
            int row = mbase + warp_m * 32 + mt * 16 + r0;
            if (row < M) {
                float a = acc[mt][nt][0], b = acc[mt][nt][1];
                s0 += a; q0 += a * a; s1 += b; q1 += b * b;
            }
            if (row + 8 < M) {
                float a = acc[mt][nt][2], b = acc[mt][nt][3];
                s0 += a; q0 += a * a; s1 += b; q1 += b * b;
            }
        }
        int col = warp_n * 48 + nt * 8 + cc;
        atomicAdd(&bns[col], s0);
        atomicAdd(&bnq[col], q0);
        atomicAdd(&bns[col + 1], s1);
        atomicAdd(&bnq[col + 1], q1);
    }
    __syncthreads();
    if (tid < 96) {
        atomicAdd(&g_bn[tid], bns[tid]);
        atomicAdd(&g_bn[96 + tid], bnq[tid]);
    }
}

// ---- 5: BN scale/shift ----
__global__ void bnscale_kernel(const float* __restrict__ gamma,
                               const float* __restrict__ beta, int M) {
    int j = threadIdx.x;
    if (j >= HID) return;
    float inv = 1.0f / (float)M;
    float mu = g_bn[j] * inv;
    float var = g_bn[HID + j] * inv - mu * mu;
    if (var < 0.0f) var = 0.0f;
    float sc = gamma[j] * rsqrtf(var + EPSBN);
    g_ss[j] = sc;
    g_ss[HID + j] = beta[j] - mu * sc;
}

// ---- 7: residual linear GEMM (fp32 SIMT) ----
__global__ __launch_bounds__(256, 2)
void linear_kernel(const float* __restrict__ hF, const float* __restrict__ qF,
                   const float* __restrict__ Wl, const float* __restrict__ bl,
                   float* __restrict__ out, int N) {
    __shared__ float As[2][TM * (KC + 1)];
    __shared__ float Bs[2][KC * HID];

    int tid = threadIdx.x;
    int nbase = blockIdx.x * TM;
    int tr = tid >> 4;
    int tc = tid & 15;

    float acc[8][6];
#pragma unroll
    for (int i = 0; i < 8; ++i)
#pragma unroll
        for (int p = 0; p < 6; ++p) acc[i][p] = 0.0f;

    {
#pragma unroll
        for (int i = 0; i < 8; ++i) {
            int idx = i * 256 + tid;
            int c = idx & (KC - 1), r = idx >> 4;
            int n = nbase + r;
            float v = 0.0f;
            if (n < N) v = hF[(size_t)n * HID + c];
            As[0][r * (KC + 1) + c] = v;
        }
#pragma unroll
        for (int i = 0; i < 6; ++i) {
            int idx = i * 256 + tid;
            Bs[0][idx] = Wl[idx];
        }
    }
    __syncthreads();
    int buf = 0;
#pragma unroll
    for (int ch = 0; ch < NCH; ++ch) {
        float ra[8], rb[6];
        if (ch < NCH - 1) {
            int cbase = (ch + 1) * KC;
#pragma unroll
            for (int i = 0; i < 8; ++i) {
                int idx = i * 256 + tid;
                int c = idx & (KC - 1), r = idx >> 4;
                int n = nbase + r;
                int col = cbase + c;
                float v = 0.0f;
                if (n < N)
                    v = (col < HID) ? hF[(size_t)n * HID + col]
                                    : qF[(size_t)n * HID + (col - HID)];
                ra[i] = v;
            }
#pragma unroll
            for (int i = 0; i < 6; ++i) {
                int idx = i * 256 + tid;
                rb[i] = Wl[(size_t)cbase * HID + idx];
            }
        }
        const float* Ab = &As[buf][0];
        const float* Bb = &Bs[buf][0];
#pragma unroll
        for (int c = 0; c < KC; ++c) {
            float a[8], b[6];
#pragma unroll
            for (int i = 0; i < 8; ++i) a[i] = Ab[(tr * 8 + i) * (KC + 1) + c];
#pragma unroll
            for (int p = 0; p < 6; ++p) b[p] = Bb[c * HID + tc * 6 + p];
#pragma unroll
            for (int i = 0; i < 8; ++i)
#pragma unroll
                for (int p = 0; p < 6; ++p) acc[i][p] += a[i] * b[p];
        }
        if (ch < NCH - 1) {
            int nb = buf ^ 1;
#pragma unroll
            for (int i = 0; i < 8; ++i) {
                int idx = i * 256 + tid;
                int c = idx & (KC - 1), r = idx >> 4;
                As[nb][r * (KC + 1) + c] = ra[i];
            }
#pragma unroll
            for (int i = 0; i < 6; ++i) Bs[nb][i * 256 + tid] = rb[i];
            __syncthreads();
            buf = nb;
        }
    }
#pragma unroll
    for (int i = 0; i < 8; ++i) {
        int n = nbase + tr * 8 + i;
        if (n < N) {
#pragma unroll
            for (int p = 0; p < 6; ++p)
                out[(size_t)n * HID + tc * 6 + p] = acc[i][p] + bl[tc * 6 + p];
        }
    }
}

// ---- 8: trilinear gather with fused BN+ReLU ----
__global__ void trilinear_kernel(const float* __restrict__ cw, const int* __restrict__ cidx,
                                 float* __restrict__ out, int N, int M) {
    long long t = (long long)blockIdx.x * blockDim.x + threadIdx.x;
    if (t >= (long long)N * HID) return;
    int n = (int)(t / HID);
    int j = (int)(t - (long long)n * HID);
    float sc = g_ss[j];
    float sh = g_ss[HID + j];
    float s = out[t];
#pragma unroll
    for (int k = 0; k < 8; ++k) {
        int ci = cidx[(size_t)n * 8 + k];
        if (ci < M) {
            float w = cw[(size_t)n * 8 + k];
            float v = g_acc[(size_t)ci * HID + j] * sc + sh;
            v = v > 0.0f ? v : 0.0f;
            s += w * v;
        }
    }
    out[t] = s;
}

extern "C" void kernel_launch(void* const* d_in, const int* in_sizes, int n_in,
                              void* d_out, int out_size) {
    const float* hF    = (const float*)d_in[0];
    const float* qF    = (const float*)d_in[1];
    const float* Wc    = (const float*)d_in[2];
    const float* gamma = (const float*)d_in[3];
    const float* beta  = (const float*)d_in[4];
    const float* Wl    = (const float*)d_in[5];
    const float* bl    = (const float*)d_in[6];
    const float* cw    = (const float*)d_in[7];
    const int*   seg   = (const int*)d_in[8];
    const int*   nbr   = (const int*)d_in[9];
    const int*   cidx  = (const int*)d_in[10];
    float* out = (float*)d_out;

    int N = in_sizes[8];
    int M = in_sizes[9] / 27;

    cudaFuncSetAttribute(conv_mma_kernel,
                         cudaFuncAttributeMaxDynamicSharedMemorySize, SMEM_CONV);

    void *pv, *pc, *pb;
    cudaGetSymbolAddress(&pv, g_vsum);
    cudaGetSymbolAddress(&pc, g_cnt);
    cudaGetSymbolAddress(&pb, g_bn);
    cudaMemsetAsync(pv, 0, (size_t)M * CIN * sizeof(float), 0);
    cudaMemsetAsync(pc, 0, (size_t)M * sizeof(float), 0);
    cudaMemsetAsync(pb, 0, 2 * HID * sizeof(float), 0);

    prep_kernel<<<NSTG, 256>>>(Wc);
    nbrT_kernel<<<(M * 27 + 255) / 256, 256>>>(nbr, M);

    long long nt;
    nt = (long long)N * CIN;
    scatter_kernel<<<(unsigned)((nt + 255) / 256), 256>>>(hF, qF, seg, N);

    nt = (long long)(M + 1) * CIN;
    split_kernel<<<(unsigned)((nt + 255) / 256), 256>>>(M);

    conv_mma_kernel<<<(M + CTM - 1) / CTM, 256, SMEM_CONV>>>(M);

    bnscale_kernel<<<1, HID>>>(gamma, beta, M);

    linear_kernel<<<(N + TM - 1) / TM, 256>>>(hF, qF, Wl, bl, out, N);

    nt = (long long)N * HID;
    trilinear_kernel<<<(unsigned)((nt + 255) / 256), 256>>>(cw, cidx, out, N, M);
}

// round 6
// speedup vs baseline: 5.3058x; 1.0272x over previous
#include <cuda_runtime.h>
#include <cuda_fp16.h>
#include <cstdint>

#define HID 96
#define CIN 192
#define MAXN 120000
#define EPSBN 1e-5f

// fp32 linear GEMM params
#define TM 128
#define KC 16
#define NCH (CIN / KC)

// ===== conv mma params =====
#define CTM 128                 // voxel rows per CTA
#define NSTG 162                // 27 offsets * 6 chunks of K=32
#define ASTRIDE 80              // bytes per smem row (32 fp16 = 64B + 16 pad)
#define AHPL (128 * ASTRIDE)    // 10240 B (one A plane: hi or lo)
#define BPL (96 * ASTRIDE)      // 7680 B
#define STG (2 * AHPL + BPL)    // 28160 B per stage
#define SMEM_CONV (2 * STG)     // 56320 B

// ---- scratch (static device globals; no allocation) ----
__device__ float g_vsum[(size_t)MAXN * CIN];
__device__ float g_cnt[MAXN];
__device__ __half g_vhl[(size_t)(MAXN + 1) * 384];   // per voxel: 192 hi | 192 lo
__device__ float g_acc[(size_t)MAXN * HID];          // conv output
__device__ float g_bn[2 * HID];
__device__ float g_ss[2 * HID];
__device__ __half g_wh[(size_t)NSTG * 96 * 32];      // fp16 weights [stage][n][k]
__device__ int g_nbrT[27 * MAXN];                    // transposed neighbor table

#define MMA_F16(d, a, b0r, b1r)                                               \
    asm volatile(                                                             \
        "mma.sync.aligned.m16n8k16.row.col.f32.f16.f16.f32 "                  \
        "{%0,%1,%2,%3},{%4,%5,%6,%7},{%8,%9},{%0,%1,%2,%3};"                  \
        : "+f"((d)[0]), "+f"((d)[1]), "+f"((d)[2]), "+f"((d)[3])              \
        : "r"((a)[0]), "r"((a)[1]), "r"((a)[2]), "r"((a)[3]),                 \
          "r"(b0r), "r"(b1r))

#define LDMX4(r, addr)                                                        \
    asm volatile(                                                             \
        "ldmatrix.sync.aligned.m8n8.x4.shared.b16 {%0,%1,%2,%3}, [%4];"       \
        : "=r"((r)[0]), "=r"((r)[1]), "=r"((r)[2]), "=r"((r)[3])              \
        : "r"(addr))

__device__ __forceinline__ uint32_t smem_u32(const void* p) {
    uint32_t a;
    asm("{ .reg .u64 t; cvta.to.shared.u64 t, %1; cvt.u32.u64 %0, t; }" : "=r"(a) : "l"(p));
    return a;
}

// ---- 0a: weight prep: transpose + fp16 ----
__global__ void prep_kernel(const float* __restrict__ W) {
    int b = blockIdx.x;                  // stage = k*6 + ch
    int k = b / 6, ch = b - k * 6;
    __half* dst = g_wh + (size_t)b * 3072;
    for (int idx = threadIdx.x; idx < 3072; idx += blockDim.x) {
        int n = idx >> 5;
        int c = idx & 31;
        dst[idx] = __float2half_rn(W[((size_t)k * CIN + (ch * 32 + c)) * HID + n]);
    }
}

// ---- 0b: transpose neighbor table ----
__global__ void nbrT_kernel(const int* __restrict__ nbr, int M) {
    int idx = blockIdx.x * blockDim.x + threadIdx.x;
    if (idx >= M * 27) return;
    int m = idx / 27, k = idx - m * 27;
    g_nbrT[k * MAXN + m] = nbr[idx];
}

// ---- 1: concat + scatter-add ----
__global__ void scatter_kernel(const float* __restrict__ hF, const float* __restrict__ qF,
                               const int* __restrict__ seg, int N) {
    long long t = (long long)blockIdx.x * blockDim.x + threadIdx.x;
    if (t >= (long long)N * CIN) return;
    int n = (int)(t / CIN);
    int c = (int)(t - (long long)n * CIN);
    float v = (c < HID) ? hF[(size_t)n * HID + c] : qF[(size_t)n * HID + (c - HID)];
    int m = seg[n];
    atomicAdd(&g_vsum[(size_t)m * CIN + c], v);
    if (c == 0) atomicAdd(&g_cnt[m], 1.0f);
}

// ---- 2: divide by count + fp16 hi/lo split -> g_vhl (row M = zeros) ----
__global__ void split_kernel(int M) {
    long long t = (long long)blockIdx.x * blockDim.x + threadIdx.x;
    if (t >= (long long)(M + 1) * CIN) return;
    int m = (int)(t / CIN);
    int c = (int)(t - (long long)m * CIN);
    __half hi = __float2half_rn(0.0f), lo = __float2half_rn(0.0f);
    if (m < M) {
        float ct = g_cnt[m];
        if (ct < 1.0f) ct = 1.0f;
        float v = g_vsum[t] / ct;
        hi = __float2half_rn(v);
        lo = __float2half_rn(v - __half2float(hi));
    }
    g_vhl[(size_t)m * 384 + c] = hi;
    g_vhl[(size_t)m * 384 + 192 + c] = lo;
}

// ---- 3: sparse conv, fp16 2-term split, ldmatrix fragments ----
__global__ __launch_bounds__(256)
void conv_mma_kernel(int M) {
    extern __shared__ char smem[];
    int tid = threadIdx.x;
    int wid = tid >> 5;
    int lane = tid & 31;
    int mbase = blockIdx.x * CTM;

    int prow = tid >> 1;          // producer row 0..127
    int ppart = tid & 1;          // 32B half within 64B row
    int warp_m = wid & 3;
    int warp_n = wid >> 2;
    int r0 = lane >> 2;

    // ldmatrix per-lane offsets (within a tile, bytes)
    uint32_t aoff = (uint32_t)(lane & 15) * ASTRIDE + (uint32_t)(lane >> 4) * 16;
    uint32_t boff = ((uint32_t)(lane & 7) + (uint32_t)(lane >> 4) * 8) * ASTRIDE
                  + (uint32_t)((lane >> 3) & 1) * 16;

    uint32_t sm0 = smem_u32(smem);

    float acc[2][6][4];
#pragma unroll
    for (int mt = 0; mt < 2; ++mt)
#pragma unroll
        for (int nt = 0; nt < 6; ++nt)
#pragma unroll
            for (int q = 0; q < 4; ++q) acc[mt][nt][q] = 0.0f;

    const char* vhl = (const char*)g_vhl;
    const char* whbase = (const char*)g_wh;

    // ---- produce stage 0 into buf 0 (direct LDG -> STS) ----
    {
        int m = mbase + prow;
        int row = (m < M) ? g_nbrT[0 * MAXN + m] : M;
        const char* sa = vhl + (size_t)row * 768 + ppart * 32;
        char* da = smem + prow * ASTRIDE + ppart * 32;
        *(uint4*)(da) = *(const uint4*)(sa);
        *(uint4*)(da + 16) = *(const uint4*)(sa + 16);
        *(uint4*)(da + AHPL) = *(const uint4*)(sa + 384);
        *(uint4*)(da + AHPL + 16) = *(const uint4*)(sa + 400);
        char* bb = smem + 2 * AHPL;
        const uint4* ws = (const uint4*)whbase;
        {
            uint4 v = ws[tid];
            *(uint4*)(bb + (tid >> 2) * ASTRIDE + (tid & 3) * 16) = v;
        }
        if (tid < 128) {
            int i2 = tid + 256;
            uint4 v = ws[i2];
            *(uint4*)(bb + (i2 >> 2) * ASTRIDE + (i2 & 3) * 16) = v;
        }
    }
    __syncthreads();

    for (int it = 0; it < NSTG; ++it) {
        int buf = it & 1;
        bool pf = (it + 1 < NSTG);
        uint4 va[4], vb0, vb1;

        // ---- register prefetch of next stage ----
        if (pf) {
            int st = it + 1;
            int k = st / 6, ch = st - k * 6;
            int m = mbase + prow;
            int row = (m < M) ? g_nbrT[k * MAXN + m] : M;
            const char* sa = vhl + (size_t)row * 768 + ch * 64 + ppart * 32;
            va[0] = *(const uint4*)(sa);
            va[1] = *(const uint4*)(sa + 16);
            va[2] = *(const uint4*)(sa + 384);
            va[3] = *(const uint4*)(sa + 400);
            const uint4* ws = (const uint4*)(whbase + (size_t)st * 6144);
            vb0 = ws[tid];
            if (tid < 128) vb1 = ws[tid + 256];
        }

        // ---- consume buf (ldmatrix fragments) ----
        {
            uint32_t ah_u = sm0 + buf * STG;
            uint32_t al_u = ah_u + AHPL;
            uint32_t bh_u = ah_u + 2 * AHPL;
            uint32_t atile = (uint32_t)(warp_m * 32) * ASTRIDE + aoff;
            uint32_t btile = (uint32_t)(warp_n * 48) * ASTRIDE + boff;
#pragma unroll
            for (int s = 0; s < 2; ++s) {
                uint32_t kb = s * 32;
                uint32_t Ah[2][4], Al[2][4], Bq[3][4];
#pragma unroll
                for (int mt = 0; mt < 2; ++mt) {
                    uint32_t ta = atile + mt * (16 * ASTRIDE) + kb;
                    LDMX4(Ah[mt], ah_u + ta);
                    LDMX4(Al[mt], al_u + ta);
                }
#pragma unroll
                for (int np = 0; np < 3; ++np) {
                    LDMX4(Bq[np], bh_u + btile + np * (16 * ASTRIDE) + kb);
                }
#pragma unroll
                for (int np = 0; np < 3; ++np) {
#pragma unroll
                    for (int mt = 0; mt < 2; ++mt) {
                        MMA_F16(acc[mt][2 * np], Ah[mt], Bq[np][0], Bq[np][1]);
                        MMA_F16(acc[mt][2 * np], Al[mt], Bq[np][0], Bq[np][1]);
                        MMA_F16(acc[mt][2 * np + 1], Ah[mt], Bq[np][2], Bq[np][3]);
                        MMA_F16(acc[mt][2 * np + 1], Al[mt], Bq[np][2], Bq[np][3]);
                    }
                }
            }
        }

        // ---- store prefetched stage into buf^1 ----
        if (pf) {
            char* stg = smem + (buf ^ 1) * STG;
            char* da = stg + prow * ASTRIDE + ppart * 32;
            *(uint4*)(da) = va[0];
            *(uint4*)(da + 16) = va[1];
            *(uint4*)(da + AHPL) = va[2];
            *(uint4*)(da + AHPL + 16) = va[3];
            char* bb = stg + 2 * AHPL;
            *(uint4*)(bb + (tid >> 2) * ASTRIDE + (tid & 3) * 16) = vb0;
            if (tid < 128) {
                int i2 = tid + 256;
                *(uint4*)(bb + (i2 >> 2) * ASTRIDE + (i2 & 3) * 16) = vb1;
            }
        }
        __syncthreads();
    }

    // ---- epilogue: store acc + fused BN partial sums ----
    int cc = (lane & 3) << 1;
#pragma unroll
    for (int mt = 0; mt < 2; ++mt) {
        int row = mbase + warp_m * 32 + mt * 16 + r0;
#pragma unroll
        for (int nt = 0; nt < 6; ++nt) {
            int col = warp_n * 48 + nt * 8 + cc;
            if (row < M)
                *(float2*)(g_acc + (size_t)row * HID + col) =
                    make_float2(acc[mt][nt][0], acc[mt][nt][1]);
            if (row + 8 < M)
                *(float2*)(g_acc + (size_t)(row + 8) * HID + col) =
                    make_float2(acc[mt][nt][2], acc[mt][nt][3]);
        }
    }

    __syncthreads();
    float* bns = (float*)smem;       // [96] sums
    float* bnq = bns + 96;           // [96] sumsq
    if (tid < 192) bns[tid] = 0.0f;
    __syncthreads();
#pragma unroll
    for (int nt = 0; nt < 6; ++nt) {
        float s0 = 0.f, q0 = 0.f, s1 = 0.f, q1 = 0.f;
#pragma unroll
        for (int mt = 0; mt < 2; ++mt) {
            int row = mbase + warp_m * 32 + mt * 16 + r0;
            if (row < M) {
                float a = acc[mt][nt][0], b = acc[mt][nt][1];
                s0 += a; q0 += a * a; s1 += b; q1 += b * b;
            }
            if (row + 8 < M) {
                float a = acc[mt][nt][2], b = acc[mt][nt][3];
                s0 += a; q0 += a * a; s1 += b; q1 += b * b;
            }
        }
        int col = warp_n * 48 + nt * 8 + cc;
        atomicAdd(&bns[col], s0);
        atomicAdd(&bnq[col], q0);
        atomicAdd(&bns[col + 1], s1);
        atomicAdd(&bnq[col + 1], q1);
    }
    __syncthreads();
    if (tid < 96) {
        atomicAdd(&g_bn[tid], bns[tid]);
        atomicAdd(&g_bn[96 + tid], bnq[tid]);
    }
}

// ---- 5: BN scale/shift ----
__global__ void bnscale_kernel(const float* __restrict__ gamma,
                               const float* __restrict__ beta, int M) {
    int j = threadIdx.x;
    if (j >= HID) return;
    float inv = 1.0f / (float)M;
    float mu = g_bn[j] * inv;
    float var = g_bn[HID + j] * inv - mu * mu;
    if (var < 0.0f) var = 0.0f;
    float sc = gamma[j] * rsqrtf(var + EPSBN);
    g_ss[j] = sc;
    g_ss[HID + j] = beta[j] - mu * sc;
}

// ---- 7: residual linear GEMM (fp32 SIMT) ----
__global__ __launch_bounds__(256, 2)
void linear_kernel(const float* __restrict__ hF, const float* __restrict__ qF,
                   const float* __restrict__ Wl, const float* __restrict__ bl,
                   float* __restrict__ out, int N) {
    __shared__ float As[2][TM * (KC + 1)];
    __shared__ float Bs[2][KC * HID];

    int tid = threadIdx.x;
    int nbase = blockIdx.x * TM;
    int tr = tid >> 4;
    int tc = tid & 15;

    float acc[8][6];
#pragma unroll
    for (int i = 0; i < 8; ++i)
#pragma unroll
        for (int p = 0; p < 6; ++p) acc[i][p] = 0.0f;

    {
#pragma unroll
        for (int i = 0; i < 8; ++i) {
            int idx = i * 256 + tid;
            int c = idx & (KC - 1), r = idx >> 4;
            int n = nbase + r;
            float v = 0.0f;
            if (n < N) v = hF[(size_t)n * HID + c];
            As[0][r * (KC + 1) + c] = v;
        }
#pragma unroll
        for (int i = 0; i < 6; ++i) {
            int idx = i * 256 + tid;
            Bs[0][idx] = Wl[idx];
        }
    }
    __syncthreads();
    int buf = 0;
#pragma unroll
    for (int ch = 0; ch < NCH; ++ch) {
        float ra[8], rb[6];
        if (ch < NCH - 1) {
            int cbase = (ch + 1) * KC;
#pragma unroll
            for (int i = 0; i < 8; ++i) {
                int idx = i * 256 + tid;
                int c = idx & (KC - 1), r = idx >> 4;
                int n = nbase + r;
                int col = cbase + c;
                float v = 0.0f;
                if (n < N)
                    v = (col < HID) ? hF[(size_t)n * HID + col]
                                    : qF[(size_t)n * HID + (col - HID)];
                ra[i] = v;
            }
#pragma unroll
            for (int i = 0; i < 6; ++i) {
                int idx = i * 256 + tid;
                rb[i] = Wl[(size_t)cbase * HID + idx];
            }
        }
        const float* Ab = &As[buf][0];
        const float* Bb = &Bs[buf][0];
#pragma unroll
        for (int c = 0; c < KC; ++c) {
            float a[8], b[6];
#pragma unroll
            for (int i = 0; i < 8; ++i) a[i] = Ab[(tr * 8 + i) * (KC + 1) + c];
#pragma unroll
            for (int p = 0; p < 6; ++p) b[p] = Bb[c * HID + tc * 6 + p];
#pragma unroll
            for (int i = 0; i < 8; ++i)
#pragma unroll
                for (int p = 0; p < 6; ++p) acc[i][p] += a[i] * b[p];
        }
        if (ch < NCH - 1) {
            int nb = buf ^ 1;
#pragma unroll
            for (int i = 0; i < 8; ++i) {
                int idx = i * 256 + tid;
                int c = idx & (KC - 1), r = idx >> 4;
                As[nb][r * (KC + 1) + c] = ra[i];
            }
#pragma unroll
            for (int i = 0; i < 6; ++i) Bs[nb][i * 256 + tid] = rb[i];
            __syncthreads();
            buf = nb;
        }
    }
#pragma unroll
    for (int i = 0; i < 8; ++i) {
        int n = nbase + tr * 8 + i;
        if (n < N) {
#pragma unroll
            for (int p = 0; p < 6; ++p)
                out[(size_t)n * HID + tc * 6 + p] = acc[i][p] + bl[tc * 6 + p];
        }
    }
}

// ---- 8: trilinear gather with fused BN+ReLU ----
__global__ void trilinear_kernel(const float* __restrict__ cw, const int* __restrict__ cidx,
                                 float* __restrict__ out, int N, int M) {
    long long t = (long long)blockIdx.x * blockDim.x + threadIdx.x;
    if (t >= (long long)N * HID) return;
    int n = (int)(t / HID);
    int j = (int)(t - (long long)n * HID);
    float sc = g_ss[j];
    float sh = g_ss[HID + j];
    float s = out[t];
#pragma unroll
    for (int k = 0; k < 8; ++k) {
        int ci = cidx[(size_t)n * 8 + k];
        if (ci < M) {
            float w = cw[(size_t)n * 8 + k];
            float v = g_acc[(size_t)ci * HID + j] * sc + sh;
            v = v > 0.0f ? v : 0.0f;
            s += w * v;
        }
    }
    out[t] = s;
}

extern "C" void kernel_launch(void* const* d_in, const int* in_sizes, int n_in,
                              void* d_out, int out_size) {
    const float* hF    = (const float*)d_in[0];
    const float* qF    = (const float*)d_in[1];
    const float* Wc    = (const float*)d_in[2];
    const float* gamma = (const float*)d_in[3];
    const float* beta  = (const float*)d_in[4];
    const float* Wl    = (const float*)d_in[5];
    const float* bl    = (const float*)d_in[6];
    const float* cw    = (const float*)d_in[7];
    const int*   seg   = (const int*)d_in[8];
    const int*   nbr   = (const int*)d_in[9];
    const int*   cidx  = (const int*)d_in[10];
    float* out = (float*)d_out;

    int N = in_sizes[8];
    int M = in_sizes[9] / 27;

    cudaFuncSetAttribute(conv_mma_kernel,
                         cudaFuncAttributeMaxDynamicSharedMemorySize, SMEM_CONV);

    void *pv, *pc, *pb;
    cudaGetSymbolAddress(&pv, g_vsum);
    cudaGetSymbolAddress(&pc, g_cnt);
    cudaGetSymbolAddress(&pb, g_bn);
    cudaMemsetAsync(pv, 0, (size_t)M * CIN * sizeof(float), 0);
    cudaMemsetAsync(pc, 0, (size_t)M * sizeof(float), 0);
    cudaMemsetAsync(pb, 0, 2 * HID * sizeof(float), 0);

    prep_kernel<<<NSTG, 256>>>(Wc);
    nbrT_kernel<<<(M * 27 + 255) / 256, 256>>>(nbr, M);

    long long nt;
    nt = (long long)N * CIN;
    scatter_kernel<<<(unsigned)((nt + 255) / 256), 256>>>(hF, qF, seg, N);

    nt = (long long)(M + 1) * CIN;
    split_kernel<<<(unsigned)((nt + 255) / 256), 256>>>(M);

    conv_mma_kernel<<<(M + CTM - 1) / CTM, 256, SMEM_CONV>>>(M);

    bnscale_kernel<<<1, HID>>>(gamma, beta, M);

    linear_kernel<<<(N + TM - 1) / TM, 256>>>(hF, qF, Wl, bl, out, N);

    nt = (long long)N * HID;
    trilinear_kernel<<<(unsigned)((nt + 255) / 256), 256>>>(cw, cidx, out, N, M);
}